// round 13
// baseline (speedup 1.0000x reference)
#include <cuda_runtime.h>
#include <math.h>

#define N     16384
#define S     8192
#define T     1024
#define GPT   16
#define CELLS 512
#define R2    0.0625f
#define KNB   10

// Distance formula matching XLA's contraction of sum((a-b)**2, -1).
__device__ __forceinline__ float dist2(float dx, float dy, float dz) {
    return fmaf(dz, dz, fmaf(dy, dy, __fmul_rn(dx, dx)));
}

__device__ __forceinline__ unsigned long long pack2(float lo, float hi) {
    unsigned long long r;
    asm("mov.b64 %0, {%1,%2};" : "=l"(r) : "f"(lo), "f"(hi));
    return r;
}
__device__ __forceinline__ void unpack2(unsigned long long v, float& lo, float& hi) {
    asm("mov.b64 {%0,%1}, %2;" : "=f"(lo), "=f"(hi) : "l"(v));
}
#define ADD2(o, a, b) asm("add.rn.f32x2 %0, %1, %2;" : "=l"(o) : "l"(a), "l"(b))
#define MUL2(o, a, b) asm("mul.rn.f32x2 %0, %1, %2;" : "=l"(o) : "l"(a), "l"(b))
#define FMA2(o, a, b, c) asm("fma.rn.f32x2 %0, %1, %2, %3;" : "=l"(o) : "l"(a), "l"(b), "l"(c))

__device__ __forceinline__ int morton3(int x, int y, int z) {
    int m = 0;
#pragma unroll
    for (int b = 0; b < 3; ++b)
        m |= (((x >> b) & 1) << (3*b)) | (((y >> b) & 1) << (3*b + 1)) |
             (((z >> b) & 1) << (3*b + 2));
    return m;
}

// ---------------- global scratch ----------------
__device__ float g_xs[N], g_ys[N], g_zs[N];
__device__ int   g_s2o[N];
__device__ int   g_fps_idx[S];
__device__ int   g_src[S * KNB];

// ---------------- K0: counting sort into Morton-ordered 8x8x8 grid ----------------
__global__ __launch_bounds__(T, 1) void sort_kernel(const float* __restrict__ pos) {
    __shared__ int hist[CELLS];
    __shared__ int scanbuf[CELLS];
    int tid = threadIdx.x;
    if (tid < CELLS) hist[tid] = 0;
    __syncthreads();
#pragma unroll
    for (int g = 0; g < GPT; ++g) {
        int i = g * T + tid;
        float x = pos[3*i], y = pos[3*i+1], z = pos[3*i+2];
        int cx = min(7, (int)(x * 8.0f));
        int cy = min(7, (int)(y * 8.0f));
        int cz = min(7, (int)(z * 8.0f));
        atomicAdd(&hist[morton3(cx, cy, cz)], 1);
    }
    __syncthreads();
    if (tid < CELLS) scanbuf[tid] = hist[tid];
    __syncthreads();
    for (int off = 1; off < CELLS; off <<= 1) {
        int v = 0;
        if (tid < CELLS) { v = scanbuf[tid]; if (tid >= off) v += scanbuf[tid - off]; }
        __syncthreads();
        if (tid < CELLS) scanbuf[tid] = v;
        __syncthreads();
    }
    if (tid < CELLS) hist[tid] = scanbuf[tid] - hist[tid];
    __syncthreads();
#pragma unroll
    for (int g = 0; g < GPT; ++g) {
        int i = g * T + tid;
        float x = pos[3*i], y = pos[3*i+1], z = pos[3*i+2];
        int cx = min(7, (int)(x * 8.0f));
        int cy = min(7, (int)(y * 8.0f));
        int cz = min(7, (int)(z * 8.0f));
        int c  = morton3(cx, cy, cz);
        int d  = atomicAdd(&hist[c], 1);
        int a  = (d & 15) * T + (d >> 4);
        g_xs[a] = x; g_ys[a] = y; g_zs[a] = z;
        g_s2o[a] = i;
    }
}

// dummy kernels: position fps_kernel at launch index 3 for ncu capture
__global__ void dummy_kernel() {}

// ---------------- K1: pruned FPS (single block, R12 structure + packed math) ----------------
// smem: pair-interleaved X/Y/Z arrays; rescan uses f32x2 add/mul/fma (per-component
// rn rounding == scalar chain, bit-exact). Tie-break unchanged: max val, then max
// key (~orig<<14)|layout == lowest original index, via tie-mask + set-bit loop.
__global__ __launch_bounds__(T, 1) void fps_kernel(const float* __restrict__ pos) {
    extern __shared__ float sm[];
    unsigned long long* sxp = (unsigned long long*)sm;      // 64KB: (x_{2j},x_{2j+1})
    unsigned long long* syp = sxp + N/2;                    // 64KB
    unsigned long long* szp = syp + N/2;                    // 64KB
    __shared__ uint2 sbest[2][32];
    int tid  = threadIdx.x;
    int lane = tid & 31;
    int wid  = tid >> 5;
    if (tid == 0) g_fps_idx[0] = 0;

    unsigned pk[GPT/2];
#pragma unroll
    for (int g = 0; g < GPT/2; ++g) pk[g] = 0u;
#pragma unroll
    for (int j = 0; j < 8; ++j) {
        int a0 = (2*j) * T + tid, a1 = (2*j + 1) * T + tid;
        sxp[j * T + tid] = pack2(g_xs[a0], g_xs[a1]);
        syp[j * T + tid] = pack2(g_ys[a0], g_ys[a1]);
        szp[j * T + tid] = pack2(g_zs[a0], g_zs[a1]);
    }
#pragma unroll
    for (int g = 0; g < GPT; ++g) {
        unsigned ko = (~(unsigned)g_s2o[g * T + tid]) & 0x3FFFu;  // max(~orig)==min(orig)
        pk[g >> 1] |= ko << (16 * (g & 1));
    }
    __syncthreads();

    // group centroid + radius (upper bound, padded)
    float qx = 0.f, qy = 0.f, qz = 0.f;
#pragma unroll
    for (int j = 0; j < 8; ++j) {
        float x0, x1, y0, y1, z0, z1;
        unpack2(sxp[j*T+tid], x0, x1); unpack2(syp[j*T+tid], y0, y1); unpack2(szp[j*T+tid], z0, z1);
        qx += x0 + x1; qy += y0 + y1; qz += z0 + z1;
    }
    qx *= (1.0f / GPT); qy *= (1.0f / GPT); qz *= (1.0f / GPT);
    float rr = 0.f;
#pragma unroll
    for (int j = 0; j < 8; ++j) {
        float x0, x1, y0, y1, z0, z1;
        unpack2(sxp[j*T+tid], x0, x1); unpack2(syp[j*T+tid], y0, y1); unpack2(szp[j*T+tid], z0, z1);
        float dx0 = x0-qx, dy0 = y0-qy, dz0 = z0-qz;
        float dx1 = x1-qx, dy1 = y1-qy, dz1 = z1-qz;
        rr = fmaxf(rr, fmaxf(dx0*dx0+dy0*dy0+dz0*dz0, dx1*dx1+dy1*dy1+dz1*dz1));
    }
    float r = sqrtf(rr) + 1e-4f;

    float m[GPT];
#pragma unroll
    for (int g = 0; g < GPT; ++g) m[g] = 3.402823466e38f;
    float    Mg   = 3.402823466e38f;
    unsigned kab  = 0u;                 // packed key (ko<<14)|layout of lane argmax
    float    thr2 = 3.402823466e38f;    // force update at t=1
    unsigned wval = 0u, wk2 = 0u;       // warp best (set at t=1)

    float cx = pos[0], cy = pos[1], cz = pos[2];

    for (int t = 1; t < S; ++t) {
        int p = t & 1;
        float dqx = qx - cx, dqy = qy - cy, dqz = qz - cz;
        float dd  = dqx*dqx + dqy*dqy + dqz*dqz;
        bool need = dd < thr2;
        unsigned upd = __ballot_sync(0xffffffffu, need);
        if (upd) {
            if (need) {
                unsigned long long ncx2 = pack2(-cx, -cx);
                unsigned long long ncy2 = pack2(-cy, -cy);
                unsigned long long ncz2 = pack2(-cz, -cz);
                float nm[GPT];
#pragma unroll
                for (int j = 0; j < 8; ++j) {
                    unsigned long long xp = sxp[j*T+tid], yp = syp[j*T+tid], zp = szp[j*T+tid];
                    unsigned long long dxp, dyp, dzp, dp;
                    ADD2(dxp, xp, ncx2);            // x + (-cx) == x - cx (exact)
                    ADD2(dyp, yp, ncy2);
                    ADD2(dzp, zp, ncz2);
                    MUL2(dp, dxp, dxp);
                    FMA2(dp, dyp, dyp, dp);
                    FMA2(dp, dzp, dzp, dp);         // == fmaf(dz,dz,fmaf(dy,dy,dx*dx))
                    float d0, d1; unpack2(dp, d0, d1);
                    nm[2*j]     = fminf(m[2*j],     d0);  m[2*j]     = nm[2*j];
                    nm[2*j + 1] = fminf(m[2*j + 1], d1);  m[2*j + 1] = nm[2*j + 1];
                }
                // max tree (depth 4)
                float t8[8], t4[4];
#pragma unroll
                for (int j = 0; j < 8; ++j) t8[j] = fmaxf(nm[j], nm[j + 8]);
#pragma unroll
                for (int j = 0; j < 4; ++j) t4[j] = fmaxf(t8[j], t8[j + 4]);
                float Ml = fmaxf(fmaxf(t4[0], t4[2]), fmaxf(t4[1], t4[3]));
                // tie mask, then iterate set bits (typically 1): max packed key
                unsigned msk = 0u;
#pragma unroll
                for (int g = 0; g < GPT; ++g) msk |= (nm[g] == Ml) ? (1u << g) : 0u;
                unsigned best = 0u;
                do {
                    int g = __ffs(msk) - 1; msk &= msk - 1;
                    unsigned h = (unsigned)g >> 1;
                    unsigned pw = pk[0];
                    pw = (h == 1) ? pk[1] : pw; pw = (h == 2) ? pk[2] : pw;
                    pw = (h == 3) ? pk[3] : pw; pw = (h == 4) ? pk[4] : pw;
                    pw = (h == 5) ? pk[5] : pw; pw = (h == 6) ? pk[6] : pw;
                    pw = (h == 7) ? pk[7] : pw;
                    unsigned ko   = (pw >> (16 * (g & 1))) & 0xFFFFu;
                    unsigned cand = (ko << 14) | (unsigned)(g * T + tid);
                    best = (cand > best) ? cand : best;
                } while (msk);
                Mg = Ml; kab = best;
                float thr = sqrtf(Mg) + r + 1e-3f;   // conservative skip bound
                thr2 = thr * thr;
            }
            unsigned vb   = __float_as_uint(Mg);
            unsigned wmax = __reduce_max_sync(0xffffffffu, vb);
            wval = wmax;
            wk2  = __reduce_max_sync(0xffffffffu, (vb == wmax) ? kab : 0u);
        }
        if (lane == 0) sbest[p][wid] = make_uint2(wval, wk2);
        __syncthreads();
        uint2    b    = sbest[p][lane];
        unsigned gmax = __reduce_max_sync(0xffffffffu, b.x);
        unsigned gk2  = __reduce_max_sync(0xffffffffu, (b.x == gmax) ? b.y : 0u);
        int w = (int)(gk2 & 0x3FFFu);
        if (tid == 0) g_fps_idx[t] = (int)((~(gk2 >> 14)) & 0x3FFFu);
        // winner coords from packed arrays (broadcast, conflict-free)
        int wi = w >> 10, wt = w & (T - 1);
        float x0, x1, y0, y1, z0, z1;
        unpack2(sxp[(wi >> 1) * T + wt], x0, x1);
        unpack2(syp[(wi >> 1) * T + wt], y0, y1);
        unpack2(szp[(wi >> 1) * T + wt], z0, z1);
        bool odd = (wi & 1) != 0;
        cx = odd ? x1 : x0; cy = odd ? y1 : y0; cz = odd ? z1 : z0;
    }
}

// ---------------- K2: top-10 nearest neighbors, 1 warp per center ----------------
__global__ __launch_bounds__(512, 1) void knn_kernel(const float* __restrict__ pos) {
    extern __shared__ float sp[];     // 3*N floats = 192KB
    int tid = threadIdx.x, lane = tid & 31, w = tid >> 5;
    const float4* p4 = (const float4*)pos;
    float4* s4 = (float4*)sp;
#pragma unroll
    for (int i = 0; i < (3 * N / 4) / 512; ++i)
        s4[i * 512 + tid] = p4[i * 512 + tid];
    __syncthreads();

    int c  = blockIdx.x * 16 + w;
    int fi = g_fps_idx[c];
    float cx = sp[3*fi], cy = sp[3*fi+1], cz = sp[3*fi+2];

    float bd[KNB]; int bi[KNB];
#pragma unroll
    for (int k = 0; k < KNB; ++k) { bd[k] = 3.402823466e38f; bi[k] = -1; }

    for (int j = 0; j < N / 32; ++j) {
        int p = j * 32 + lane;
        float dx = __fsub_rn(sp[3*p],     cx);
        float dy = __fsub_rn(sp[3*p + 1], cy);
        float dz = __fsub_rn(sp[3*p + 2], cz);
        float d  = dist2(dx, dy, dz);
        if (d < bd[KNB - 1]) {
            bd[KNB - 1] = d; bi[KNB - 1] = p;
#pragma unroll
            for (int k = KNB - 1; k > 0; --k) {
                if (bd[k] < bd[k - 1]) {
                    float td = bd[k]; bd[k] = bd[k-1]; bd[k-1] = td;
                    int   ti = bi[k]; bi[k] = bi[k-1]; bi[k-1] = ti;
                } else break;
            }
        }
    }

    int cur = 0;
    for (int o = 0; o < KNB; ++o) {
        float hd_f; int hp;
        {
            float fv = bd[0]; int iv = bi[0];
#pragma unroll
            for (int k = 1; k < KNB; ++k) { fv = (cur == k) ? bd[k] : fv; iv = (cur == k) ? bi[k] : iv; }
            hd_f = fv; hp = iv;
        }
        unsigned hd   = __float_as_uint(hd_f);
        unsigned dmin = __reduce_min_sync(0xffffffffu, hd);
        int cand = (hd == dmin) ? hp : 0x7FFFFFFF;
        int pmin = (int)__reduce_min_sync(0xffffffffu, (unsigned)cand);
        if (lane == 0)
            g_src[c * KNB + o] = (__uint_as_float(dmin) <= R2) ? pmin : -1;
        if (hd == dmin && hp == pmin) cur++;
    }
}

// ---------------- K3: MLP (3->64 relu ->128) + max over valid neighbors ----------------
__global__ __launch_bounds__(128, 4) void mlp_kernel(const float* __restrict__ pos,
                                                     const float* __restrict__ W1,
                                                     const float* __restrict__ b1,
                                                     const float* __restrict__ W2,
                                                     const float* __restrict__ b2,
                                                     float* __restrict__ out) {
    __shared__ float h1[2][64];
    __shared__ int   ssrc[KNB];
    int tid  = threadIdx.x;
    int half = tid >> 6;
    int hid  = tid & 63;
    float w2r[64];
#pragma unroll
    for (int k = 0; k < 64; ++k) w2r[k] = W2[k * 128 + tid];
    float b2t = b2[tid];
    float w1x = W1[hid], w1y = W1[64 + hid], w1z = W1[128 + hid], b1k = b1[hid];

    for (int ci = 0; ci < 8; ++ci) {
        int i = blockIdx.x * 8 + ci;
        __syncthreads();
        if (tid < KNB) ssrc[tid] = g_src[i * KNB + tid];
        float pix = pos[3*i], piy = pos[3*i+1], piz = pos[3*i+2];
        __syncthreads();
        int cnt = 0;
#pragma unroll
        for (int k = 0; k < KNB; ++k) cnt += (ssrc[k] >= 0);
        float mx = __int_as_float(0xff800000);
        for (int nb = 0; nb < cnt; nb += 2) {
            int mynb = nb + half;
            if (mynb < cnt) {
                int sp = ssrc[mynb];
                float rx = pos[3*sp]     - pix;
                float ry = pos[3*sp + 1] - piy;
                float rz = pos[3*sp + 2] - piz;
                float h = fmaf(rz, w1z, fmaf(ry, w1y, __fmul_rn(rx, w1x))) + b1k;
                h1[half][hid] = fmaxf(h, 0.0f);
            }
            __syncthreads();
            float acc = b2t;
#pragma unroll
            for (int k = 0; k < 64; ++k) acc = fmaf(h1[0][k], w2r[k], acc);
            mx = fmaxf(mx, acc);
            if (nb + 1 < cnt) {
                float acc1 = b2t;
#pragma unroll
                for (int k = 0; k < 64; ++k) acc1 = fmaf(h1[1][k], w2r[k], acc1);
                mx = fmaxf(mx, acc1);
            }
            __syncthreads();
        }
        out[i * 128 + tid] = (cnt > 0) ? mx : 0.0f;
    }
}

// ---------------- K4: zero tail rows [S, N) ----------------
__global__ void zero_tail_kernel(float* __restrict__ out) {
    int i = blockIdx.x * blockDim.x + threadIdx.x;
    float4* o = (float4*)(out + S * 128);
    o[i] = make_float4(0.f, 0.f, 0.f, 0.f);
}

extern "C" void kernel_launch(void* const* d_in, const int* in_sizes, int n_in,
                              void* d_out, int out_size) {
    const float* pos = (const float*)d_in[0];
    const float* W1 = (const float*)d_in[2];
    const float* b1 = (const float*)d_in[3];
    const float* W2 = (const float*)d_in[4];
    const float* b2 = (const float*)d_in[5];
    float* out = (float*)d_out;

    static bool attr_set = false;
    if (!attr_set) {
        cudaFuncSetAttribute(fps_kernel, cudaFuncAttributeMaxDynamicSharedMemorySize,
                             3 * N * (int)sizeof(float));
        cudaFuncSetAttribute(knn_kernel, cudaFuncAttributeMaxDynamicSharedMemorySize,
                             3 * N * (int)sizeof(float));
        attr_set = true;
    }

    sort_kernel<<<1, T>>>(pos);
    dummy_kernel<<<1, 32>>>();                 // pad launch indices so fps lands at
    dummy_kernel<<<1, 32>>>();                 // the slot ncu captures
    fps_kernel<<<1, T, 3 * N * sizeof(float)>>>(pos);
    knn_kernel<<<S / 16, 512, 3 * N * sizeof(float)>>>(pos);
    mlp_kernel<<<S / 8, 128>>>(pos, W1, b1, W2, b2, out);
    zero_tail_kernel<<<(S * 128 / 4) / 256, 256>>>(out);
}